// round 15
// baseline (speedup 1.0000x reference)
#include <cuda_runtime.h>
#include <cuda_fp16.h>

#define BB 64
#define SS 1024
#define DD 16
#define NSPLIT 4
#define TOK (BB * SS)
#define HB (BB / 2)            // batches per pipeline half
#define HTOK (HB * SS)         // tokens per half

// Scratch (allocation-free rule: __device__ globals)
__device__ float4 g_part[NSPLIT * TOK]; // per-split partial (l, a0, a1, 0)
__device__ float2 g_q[TOK];             // q pre-scaled by 0.25*log2(e)
__device__ uint4  g_kvh[TOK];           // packed half2: (k0k0, k1k1, v0v0, v1v1)
__device__ float  g_A[256];             // diag(g) @ (W1W2W3 + I)
__device__ float  g_csA[16];            // column sums of g_A
__device__ float  g_bA[16];             // b @ (W1W2W3+I) + bc
__device__ float  g_O[256];             // diag(g) @ Wo
__device__ float  g_csO[16];            // column sums of g_O
__device__ float  g_bO[16];             // b @ Wo + bo

// ---------------------------------------------------------------------------
// Kernel 1: QKV projection for HTOK tokens starting at tok0; if the grid has
// an extra block (half A), it performs the epilogue weight folds.
// ---------------------------------------------------------------------------
__global__ void __launch_bounds__(256)
qkv_precomp_kernel(int tok0,
                   const float* __restrict__ x,
                   const float* __restrict__ Wq, const float* __restrict__ bq,
                   const float* __restrict__ Wk, const float* __restrict__ bk,
                   const float* __restrict__ Wv, const float* __restrict__ bv,
                   const float* __restrict__ W1, const float* __restrict__ b1,
                   const float* __restrict__ W2, const float* __restrict__ b2,
                   const float* __restrict__ W3, const float* __restrict__ b3,
                   const float* __restrict__ ln_g, const float* __restrict__ ln_b,
                   const float* __restrict__ Wo, const float* __restrict__ bo)
{
    int tid = threadIdx.x;

    if (blockIdx.x == HTOK / 256) {   // only present in half-A's grid
        // ------- precompute folded epilogue weights -------
        __shared__ float s1[256], s2[256], s3[256], s12[256];
        __shared__ float sA[256], sAraw[256], sO[256];
        __shared__ float sbp[16], sbc[16], sg[16], sb[16];
        int r = tid >> 4, c = tid & 15;
        s1[tid] = W1[tid]; s2[tid] = W2[tid]; s3[tid] = W3[tid];
        if (tid < 16) { sg[tid] = ln_g[tid]; sb[tid] = ln_b[tid]; }
        __syncthreads();

        float acc = 0.f;
        #pragma unroll
        for (int k = 0; k < 16; k++) acc = fmaf(s1[r*16+k], s2[k*16+c], acc);
        s12[tid] = acc;
        if (tid < 16) {                 // b1@W2 + b2
            float t = b2[tid];
            #pragma unroll
            for (int k = 0; k < 16; k++) t = fmaf(b1[k], s2[k*16+tid], t);
            sbp[tid] = t;
        }
        __syncthreads();

        float w123 = 0.f;
        #pragma unroll
        for (int k = 0; k < 16; k++) w123 = fmaf(s12[r*16+k], s3[k*16+c], w123);
        float A = w123 + (r == c ? 1.0f : 0.0f);   // residual folded in
        sAraw[tid] = A;
        sA[tid] = sg[r] * A;
        sO[tid] = sg[r] * Wo[tid];
        if (tid < 16) {                 // bc = (b1@W2+b2)@W3 + b3
            float t = b3[tid];
            #pragma unroll
            for (int k = 0; k < 16; k++) t = fmaf(sbp[k], s3[k*16+tid], t);
            sbc[tid] = t;
        }
        __syncthreads();

        g_A[tid] = sA[tid];
        g_O[tid] = sO[tid];
        if (tid < 16) {
            float cs = 0.f, bb = sbc[tid];
            float cso = 0.f, bb2 = bo[tid];
            #pragma unroll
            for (int i = 0; i < 16; i++) {
                cs  += sA[i*16+tid];
                bb   = fmaf(sb[i], sAraw[i*16+tid], bb);
                cso += sO[i*16+tid];
                bb2  = fmaf(sb[i], Wo[i*16+tid], bb2);
            }
            g_csA[tid] = cs;  g_bA[tid] = bb;
            g_csO[tid] = cso; g_bO[tid] = bb2;
        }
        return;
    }

    // ------- QKV projection -------
    __shared__ float sw[102];
    if (tid < 32)        sw[tid] = Wq[tid];
    else if (tid < 64)   sw[tid] = Wk[tid - 32];
    else if (tid < 96)   sw[tid] = Wv[tid - 64];
    else if (tid < 98)   sw[tid] = bq[tid - 96];
    else if (tid < 100)  sw[tid] = bk[tid - 98];
    else if (tid < 102)  sw[tid] = bv[tid - 100];
    __syncthreads();

    int idx = tok0 + blockIdx.x * 256 + tid;
    const float4* xp = reinterpret_cast<const float4*>(x + idx * DD);
    float xv[16];
    #pragma unroll
    for (int c4 = 0; c4 < 4; c4++) {
        float4 v = xp[c4];
        xv[4*c4+0] = v.x; xv[4*c4+1] = v.y; xv[4*c4+2] = v.z; xv[4*c4+3] = v.w;
    }

    float q0 = sw[96], q1 = sw[97];
    float k0 = sw[98], k1 = sw[99];
    float v0 = sw[100], v1 = sw[101];
    #pragma unroll
    for (int i = 0; i < 16; i++) {
        float xi = xv[i];
        q0 = fmaf(xi, sw[i*2+0],    q0);
        q1 = fmaf(xi, sw[i*2+1],    q1);
        k0 = fmaf(xi, sw[32+i*2+0], k0);
        k1 = fmaf(xi, sw[32+i*2+1], k1);
        v0 = fmaf(xi, sw[64+i*2+0], v0);
        v1 = fmaf(xi, sw[64+i*2+1], v1);
    }

    const float SC = 0.25f * 1.4426950408889634f;
    g_q[idx] = make_float2(q0 * SC, q1 * SC);

    __half2 hk0 = __floats2half2_rn(k0, k0);
    __half2 hk1 = __floats2half2_rn(k1, k1);
    __half2 hv0 = __floats2half2_rn(v0, v0);
    __half2 hv1 = __floats2half2_rn(v1, v1);
    uint4 pk;
    pk.x = *reinterpret_cast<unsigned int*>(&hk0);
    pk.y = *reinterpret_cast<unsigned int*>(&hk1);
    pk.z = *reinterpret_cast<unsigned int*>(&hv0);
    pk.w = *reinterpret_cast<unsigned int*>(&hv1);
    g_kvh[idx] = pk;
}

// ---------------------------------------------------------------------------
// Kernel 2: attention (R14 f16x2 form), batches [b0, b0+HB).
// Grid (2, NSPLIT, HB), 256 threads.
// ---------------------------------------------------------------------------
__global__ void __launch_bounds__(256)
attn_kernel(int b0)
{
    __shared__ uint4 skv[256];

    int tid   = threadIdx.x;
    int b     = b0 + blockIdx.z;
    int split = blockIdx.y;
    int chunk = blockIdx.x;

    int idx0 = b * SS + chunk * 512 + tid;
    int idx1 = idx0 + 256;

    uint4 kvrow = g_kvh[b * SS + split * 256 + tid];
    float2 qa = g_q[idx0];
    float2 qb = g_q[idx1];

    skv[tid] = kvrow;

    __half2 qx = __floats2half2_rn(qa.x, qb.x);
    __half2 qy = __floats2half2_rn(qa.y, qb.y);
    __syncthreads();

    float l0 = 0.f, a00 = 0.f, a01 = 0.f;
    float l1 = 0.f, a10 = 0.f, a11 = 0.f;

    #pragma unroll
    for (int cch = 0; cch < 16; cch++) {
        __half2 lacc  = __floats2half2_rn(0.f, 0.f);
        __half2 a0acc = lacc, a1acc = lacc;
        #pragma unroll
        for (int t = 0; t < 16; t++) {
            uint4 kv = skv[cch * 16 + t];
            __half2 k00 = *reinterpret_cast<__half2*>(&kv.x);
            __half2 k11 = *reinterpret_cast<__half2*>(&kv.y);
            __half2 v00 = *reinterpret_cast<__half2*>(&kv.z);
            __half2 v11 = *reinterpret_cast<__half2*>(&kv.w);
            __half2 d = __hfma2(qy, k11, __hmul2(qx, k00));
            __half2 p = h2exp2(d);
            lacc  = __hadd2(lacc, p);
            a0acc = __hfma2(p, v00, a0acc);
            a1acc = __hfma2(p, v11, a1acc);
        }
        float2 lf  = __half22float2(lacc);
        float2 a0f = __half22float2(a0acc);
        float2 a1f = __half22float2(a1acc);
        l0 += lf.x;  l1 += lf.y;
        a00 += a0f.x; a10 += a0f.y;
        a01 += a1f.x; a11 += a1f.y;
    }

    g_part[split * TOK + idx0] = make_float4(l0, a00, a01, 0.f);
    g_part[split * TOK + idx1] = make_float4(l1, a10, a11, 0.f);
}

// ---------------------------------------------------------------------------
// Kernel 3: epilogue (R11/R14 measured-best form), tokens [tok0, tok0+HTOK).
// ---------------------------------------------------------------------------
__global__ void __launch_bounds__(256)
epilogue_kernel(int tok0,
                const float* __restrict__ x,
                const float* __restrict__ Wu, const float* __restrict__ bu,
                float* __restrict__ out)
{
    __shared__ __align__(16) float sA[256], sO[256], sWu[32];
    __shared__ float sbu[16], scsA[16], sbA[16], scsO[16], sbO[16];

    int tid = threadIdx.x;
    int idx = tok0 + blockIdx.x * 256 + tid;

    float4 p0 = g_part[0 * TOK + idx];
    float4 p1 = g_part[1 * TOK + idx];
    float4 p2 = g_part[2 * TOK + idx];
    float4 p3 = g_part[3 * TOK + idx];
    const float4* xp = reinterpret_cast<const float4*>(x + idx * DD);
    float4 xv0 = xp[0], xv1 = xp[1], xv2 = xp[2], xv3 = xp[3];

    sA[tid] = g_A[tid]; sO[tid] = g_O[tid];
    if (tid < 32) sWu[tid] = Wu[tid];
    if (tid < 16) {
        sbu[tid] = bu[tid];
        scsA[tid] = g_csA[tid]; sbA[tid] = g_bA[tid];
        scsO[tid] = g_csO[tid]; sbO[tid] = g_bO[tid];
    }
    __syncthreads();

    float l  = p0.x + p1.x + p2.x + p3.x;
    float a0 = p0.y + p1.y + p2.y + p3.y;
    float a1 = p0.z + p1.z + p2.z + p3.z;
    float inv = 1.0f / l;
    float c0 = a0 * inv, c1 = a1 * inv;

    float xr[16] = {xv0.x, xv0.y, xv0.z, xv0.w, xv1.x, xv1.y, xv1.z, xv1.w,
                    xv2.x, xv2.y, xv2.z, xv2.w, xv3.x, xv3.y, xv3.z, xv3.w};

    float u[16];
    #pragma unroll
    for (int i = 0; i < 16; i++)
        u[i] = fmaf(c0, sWu[i], fmaf(c1, sWu[16 + i], sbu[i])) + xr[i];

    float su = 0.f, s2 = 0.f;
    #pragma unroll
    for (int i = 0; i < 16; i++) { su += u[i]; s2 = fmaf(u[i], u[i], s2); }
    float mu = su * (1.0f / 16.0f);
    float r  = rsqrtf(fmaf(-mu, mu, s2 * (1.0f / 16.0f)) + 1e-5f);

    float f[16];
    {
        float acc[16];
        #pragma unroll
        for (int j = 0; j < 16; j++) acc[j] = 0.f;
        #pragma unroll
        for (int i = 0; i < 16; i++) {
            float hv = u[i];
            const float4* wr = reinterpret_cast<const float4*>(sA + i * 16);
            #pragma unroll
            for (int j4 = 0; j4 < 4; j4++) {
                float4 w = wr[j4];
                acc[4*j4+0] = fmaf(hv, w.x, acc[4*j4+0]);
                acc[4*j4+1] = fmaf(hv, w.y, acc[4*j4+1]);
                acc[4*j4+2] = fmaf(hv, w.z, acc[4*j4+2]);
                acc[4*j4+3] = fmaf(hv, w.w, acc[4*j4+3]);
            }
        }
        #pragma unroll
        for (int j = 0; j < 16; j++)
            f[j] = fmaf(r, fmaf(-mu, scsA[j], acc[j]), sbA[j]);
    }

    float sf = 0.f, sf2 = 0.f;
    #pragma unroll
    for (int i = 0; i < 16; i++) { sf += f[i]; sf2 = fmaf(f[i], f[i], sf2); }
    float mu2 = sf * (1.0f / 16.0f);
    float r2  = rsqrtf(fmaf(-mu2, mu2, sf2 * (1.0f / 16.0f)) + 1e-5f);

    float o[16];
    {
        float acc[16];
        #pragma unroll
        for (int j = 0; j < 16; j++) acc[j] = 0.f;
        #pragma unroll
        for (int i = 0; i < 16; i++) {
            float hv = f[i];
            const float4* wr = reinterpret_cast<const float4*>(sO + i * 16);
            #pragma unroll
            for (int j4 = 0; j4 < 4; j4++) {
                float4 w = wr[j4];
                acc[4*j4+0] = fmaf(hv, w.x, acc[4*j4+0]);
                acc[4*j4+1] = fmaf(hv, w.y, acc[4*j4+1]);
                acc[4*j4+2] = fmaf(hv, w.z, acc[4*j4+2]);
                acc[4*j4+3] = fmaf(hv, w.w, acc[4*j4+3]);
            }
        }
        #pragma unroll
        for (int j = 0; j < 16; j++)
            o[j] = fmaf(r2, fmaf(-mu2, scsO[j], acc[j]), sbO[j]);
    }

    float4* op = reinterpret_cast<float4*>(out + idx * DD);
    #pragma unroll
    for (int c4 = 0; c4 < 4; c4++)
        op[c4] = make_float4(o[4*c4+0], o[4*c4+1], o[4*c4+2], o[4*c4+3]);
}

// ---------------------------------------------------------------------------
// Two-stream batch-halved pipeline. Stream/event objects are created once
// (host-side only; no device memory). Fork/join via events so graph capture
// records a DAG: half-B chain runs concurrently with half-A chain.
// ---------------------------------------------------------------------------
extern "C" void kernel_launch(void* const* d_in, const int* in_sizes, int n_in,
                              void* d_out, int out_size)
{
    const float* x    = (const float*)d_in[0];
    const float* Wq   = (const float*)d_in[1];
    const float* bq   = (const float*)d_in[2];
    const float* Wk   = (const float*)d_in[3];
    const float* bk   = (const float*)d_in[4];
    const float* Wv   = (const float*)d_in[5];
    const float* bv   = (const float*)d_in[6];
    const float* Wu   = (const float*)d_in[7];
    const float* bu   = (const float*)d_in[8];
    const float* ln_g = (const float*)d_in[9];
    const float* ln_b = (const float*)d_in[10];
    const float* W1   = (const float*)d_in[11];
    const float* b1   = (const float*)d_in[12];
    const float* W2   = (const float*)d_in[13];
    const float* b2   = (const float*)d_in[14];
    const float* W3   = (const float*)d_in[15];
    const float* b3   = (const float*)d_in[16];
    const float* Wo   = (const float*)d_in[17];
    const float* bo   = (const float*)d_in[18];
    float* out = (float*)d_out;

    static cudaStream_t sB = nullptr;
    static cudaEvent_t eStart = nullptr, eQA = nullptr, eEnd = nullptr;
    if (sB == nullptr) {
        cudaStreamCreateWithFlags(&sB, cudaStreamNonBlocking);
        cudaEventCreateWithFlags(&eStart, cudaEventDisableTiming);
        cudaEventCreateWithFlags(&eQA,    cudaEventDisableTiming);
        cudaEventCreateWithFlags(&eEnd,   cudaEventDisableTiming);
    }

    // Fork: half-B stream joins the capture via eStart.
    cudaEventRecord(eStart, 0);
    cudaStreamWaitEvent(sB, eStart, 0);

    // ---- half A on stream 0 (carries the weight-fold precomp block) ----
    qkv_precomp_kernel<<<HTOK / 256 + 1, 256, 0, 0>>>(
        0, x, Wq, bq, Wk, bk, Wv, bv,
        W1, b1, W2, b2, W3, b3, ln_g, ln_b, Wo, bo);
    cudaEventRecord(eQA, 0);   // precomp + qkv(A) done

    // ---- half B on stream sB ----
    qkv_precomp_kernel<<<HTOK / 256, 256, 0, sB>>>(
        HTOK, x, Wq, bq, Wk, bk, Wv, bv,
        W1, b1, W2, b2, W3, b3, ln_g, ln_b, Wo, bo);

    dim3 agrid(2, NSPLIT, HB);
    attn_kernel<<<agrid, 256, 0, 0>>>(0);       // half A
    attn_kernel<<<agrid, 256, 0, sB>>>(HB);     // half B

    epilogue_kernel<<<HTOK / 256, 256, 0, 0>>>(0, x, Wu, bu, out);  // half A

    cudaStreamWaitEvent(sB, eQA, 0);  // epi(B) needs folded weights from qkv(A)
    epilogue_kernel<<<HTOK / 256, 256, 0, sB>>>(HTOK, x, Wu, bu, out);  // half B

    // Join: stream 0 is the graph leaf.
    cudaEventRecord(eEnd, sB);
    cudaStreamWaitEvent(0, eEnd, 0);
}